// round 8
// baseline (speedup 1.0000x reference)
#include <cuda_runtime.h>
#include <cuda_fp16.h>

// Problem constants
#define B_  256
#define I_  128
#define J_  128
#define H_  32
#define FP_ 8          // padded feature count; f7 = 1.0 bias lane
#define ITILE 32
#define IBLKS (I_ / ITILE)   // 4

// Scratch (allocation-free rule: __device__ globals)
__device__ __align__(16) __half g_feats_h[I_ * B_ * FP_];  // [i][b][f0..f7]

__device__ __forceinline__ unsigned u32h2(__half2 h) {
    return *reinterpret_cast<unsigned*>(&h);
}
__device__ __forceinline__ unsigned hfma2u(unsigned a, unsigned b, unsigned c) {
    unsigned d;
    asm("fma.rn.f16x2 %0, %1, %2, %3;" : "=r"(d) : "r"(a), "r"(b), "r"(c));
    return d;
}
__device__ __forceinline__ unsigned tanh2u(unsigned a) {
    unsigned d;
    asm("tanh.approx.f16x2 %0, %1;" : "=r"(d) : "r"(a));
    return d;
}

// Kernel 0: zero the output (it's poisoned 0xAA; main kernel accumulates atomically)
__global__ void zero_kernel(float* __restrict__ out) {
    out[blockIdx.x * 1024 + threadIdx.x] = 0.0f;
}

// Kernel 1: feats[i][b][8] = half{x, sin x, sin 2x, sin 4x, cos x, cos 2x, cos 4x, 1}
__global__ __launch_bounds__(256) void feats_kernel(const float* __restrict__ x) {
    int t = blockIdx.x * 256 + threadIdx.x;   // t = b*I + i
    int b = t >> 7, i = t & 127;
    float xi = x[t];                          // coalesced
    float s1, c1, s2, c2, s4, c4;
    __sincosf(xi, &s1, &c1);
    __sincosf(2.0f * xi, &s2, &c2);
    __sincosf(4.0f * xi, &s4, &c4);
    __half2 p0 = __floats2half2_rn(xi, s1);
    __half2 p1 = __floats2half2_rn(s2, s4);
    __half2 p2 = __floats2half2_rn(c1, c2);
    __half2 p3 = __floats2half2_rn(c4, 1.0f);  // f7 = bias lane
    uint4 v = make_uint4(u32h2(p0), u32h2(p1), u32h2(p2), u32h2(p3));
    *reinterpret_cast<uint4*>(&g_feats_h[((size_t)i * B_ + b) * FP_]) = v;
}

// Kernel 2: block = (i-tile of 32, j), 128 threads (4 warps), 512 blocks total.
// 128-reg budget (occ 4) so all 4 mt MMA->tanh->MMA chains stay live (ILP).
// Epilogue: atomicAdd directly into out[b*J + j].
__global__ void __launch_bounds__(128, 4) kan_main_kernel(
    const float* __restrict__ W1,   // [I,J,H,7]
    const float* __restrict__ W2,   // [I,J,1,H]
    const float* __restrict__ B1,   // [I,J,H]
    const float* __restrict__ B2,   // [I,J,1]
    float* __restrict__ out)        // [B,J]
{
    __shared__ __align__(16) __half w1h[ITILE][H_][FP_];  // 0.5*W1, f7 = 0.5*B1
    __shared__ __align__(4)  __half w2h[ITILE][H_];       // W2 as half
    __shared__ float b2s[ITILE];

    const int j   = blockIdx.y;
    const int i0  = blockIdx.x * ITILE;
    const int tid = threadIdx.x;

    // Stage 0.5*W1 (branch-free; contiguous 224-float segments per il)
    for (int idx = tid; idx < ITILE * H_ * 7; idx += 128) {
        int il = idx / (H_ * 7);
        int r  = idx % (H_ * 7);          // r = h*7 + f
        size_t ij = (size_t)(i0 + il) * J_ + j;
        w1h[il][r / 7][r % 7] = __float2half(0.5f * W1[ij * (H_ * 7) + r]);
    }
    // Stage 0.5*B1 into f7 slot, W2 as half
    for (int idx = tid; idx < ITILE * H_; idx += 128) {
        int il = idx >> 5, h = idx & 31;
        size_t base = ((size_t)(i0 + il) * J_ + j) * H_ + h;
        w1h[il][h][7] = __float2half(0.5f * B1[base]);
        w2h[il][h]    = __float2half(W2[base]);
    }
    if (tid < ITILE) b2s[tid] = B2[(size_t)(i0 + tid) * J_ + j];
    __syncthreads();

    const int lane = tid & 31, warp = tid >> 5;
    const int gid = lane >> 2;      // fragment row selector
    const int tig = lane & 3;       // fragment col selector
    const int wbase = warp * 64;

    float bsum = 0.0f;
    #pragma unroll
    for (int il = 0; il < ITILE; il++) bsum += b2s[il];

    float acc[4][4] = {};           // [m-tile][k16-MMA D regs]
    const unsigned zero = 0;

    for (int il = 0; il < ITILE; il++) {
        const __half* fbase = g_feats_h + (size_t)(i0 + il) * (B_ * FP_);

        // A fragments for all 4 m-tiles (coalesced LDG, reused across both hgp)
        unsigned A0[4], A1[4];
        #pragma unroll
        for (int mt = 0; mt < 4; mt++) {
            int brow = wbase + mt * 16 + gid;
            A0[mt] = *reinterpret_cast<const unsigned*>(fbase + brow * FP_ + tig * 2);
            A1[mt] = *reinterpret_cast<const unsigned*>(fbase + (brow + 8) * FP_ + tig * 2);
        }

        #pragma unroll
        for (int hgp = 0; hgp < 2; hgp++) {
            const int h0 = hgp * 16;
            unsigned wf0 = *reinterpret_cast<const unsigned*>(&w1h[il][h0 + gid][tig * 2]);
            unsigned wf1 = *reinterpret_cast<const unsigned*>(&w1h[il][h0 + 8 + gid][tig * 2]);
            unsigned wb0 = *reinterpret_cast<const unsigned*>(&w2h[il][h0 + tig * 2]);
            unsigned wb1 = *reinterpret_cast<const unsigned*>(&w2h[il][h0 + 8 + tig * 2]);

            #pragma unroll
            for (int mt = 0; mt < 4; mt++) {
                // u-MMA, fp16 accumulator: D regs are f16x2
                unsigned u0, u1, u2, u3;
                asm volatile(
                    "mma.sync.aligned.m16n8k8.row.col.f16.f16.f16.f16 "
                    "{%0,%1}, {%2,%3}, {%4}, {%5,%6};"
                    : "=r"(u0), "=r"(u1)
                    : "r"(A0[mt]), "r"(A1[mt]), "r"(wf0), "r"(zero), "r"(zero));
                asm volatile(
                    "mma.sync.aligned.m16n8k8.row.col.f16.f16.f16.f16 "
                    "{%0,%1}, {%2,%3}, {%4}, {%5,%6};"
                    : "=r"(u2), "=r"(u3)
                    : "r"(A0[mt]), "r"(A1[mt]), "r"(wf1), "r"(zero), "r"(zero));

                // silu(t) = u + u*tanh(u), u = t/2 — pure f16x2
                unsigned s0 = hfma2u(u0, tanh2u(u0), u0);
                unsigned s1 = hfma2u(u1, tanh2u(u1), u1);
                unsigned s2 = hfma2u(u2, tanh2u(u2), u2);
                unsigned s3 = hfma2u(u3, tanh2u(u3), u3);

                // h-contraction: m16n8k16, B = W2 replicated over n, fp32 acc
                asm volatile(
                    "mma.sync.aligned.m16n8k16.row.col.f32.f16.f16.f32 "
                    "{%0,%1,%2,%3}, {%4,%5,%6,%7}, {%8,%9}, {%0,%1,%2,%3};"
                    : "+f"(acc[mt][0]), "+f"(acc[mt][1]),
                      "+f"(acc[mt][2]), "+f"(acc[mt][3])
                    : "r"(s0), "r"(s1), "r"(s2), "r"(s3), "r"(wb0), "r"(wb1));
            }
        }
    }

    // Epilogue: tig==0 lanes hold per-b sums (W2 B-operand replicated over n cols).
    // Atomic-accumulate straight into out[b*J + j].
    if (tig == 0) {
        #pragma unroll
        for (int mt = 0; mt < 4; mt++) {
            int brow = wbase + mt * 16 + gid;
            atomicAdd(&out[(size_t)brow * J_ + j],       acc[mt][0] + bsum);
            atomicAdd(&out[(size_t)(brow + 8) * J_ + j], acc[mt][2] + bsum);
        }
    }
}

extern "C" void kernel_launch(void* const* d_in, const int* in_sizes, int n_in,
                              void* d_out, int out_size) {
    const float* x  = (const float*)d_in[0];
    const float* W1 = (const float*)d_in[1];
    const float* W2 = (const float*)d_in[2];
    const float* B1 = (const float*)d_in[3];
    const float* B2 = (const float*)d_in[4];
    float* out = (float*)d_out;

    zero_kernel<<<(B_ * J_) / 1024, 1024>>>(out);
    feats_kernel<<<(B_ * I_) / 256, 256>>>(x);
    kan_main_kernel<<<dim3(IBLKS, J_), 128>>>(W1, W2, B1, B2, out);
}

// round 9
// speedup vs baseline: 1.2074x; 1.2074x over previous
#include <cuda_runtime.h>
#include <cuda_fp16.h>

// Problem constants
#define B_  256
#define I_  128
#define J_  128
#define H_  32
#define FP_ 8          // padded feature count; f7 = 1.0 bias lane
#define ITILE 16
#define IBLKS (I_ / ITILE)   // 8

// Scratch (allocation-free rule: __device__ globals)
__device__ __align__(16) __half g_feats_h[I_ * B_ * FP_];  // [i][b][f0..f7]

__device__ __forceinline__ unsigned u32h2(__half2 h) {
    return *reinterpret_cast<unsigned*>(&h);
}
__device__ __forceinline__ unsigned hfma2u(unsigned a, unsigned b, unsigned c) {
    unsigned d;
    asm("fma.rn.f16x2 %0, %1, %2, %3;" : "=r"(d) : "r"(a), "r"(b), "r"(c));
    return d;
}
__device__ __forceinline__ unsigned tanh2u(unsigned a) {
    unsigned d;
    asm("tanh.approx.f16x2 %0, %1;" : "=r"(d) : "r"(a));
    return d;
}

// Kernel 1: feats[i][b][8] = half{x, sin x, sin 2x, sin 4x, cos x, cos 2x, cos 4x, 1}
// Also zeroes out[t] (B*J == B*I == 32768 threads) so main can atomically accumulate.
__global__ __launch_bounds__(256) void feats_kernel(const float* __restrict__ x,
                                                    float* __restrict__ out) {
    int t = blockIdx.x * 256 + threadIdx.x;   // t = b*I + i
    out[t] = 0.0f;                            // B*J elements, exact cover
    int b = t >> 7, i = t & 127;
    float xi = x[t];                          // coalesced
    float s1, c1, s2, c2, s4, c4;
    __sincosf(xi, &s1, &c1);
    __sincosf(2.0f * xi, &s2, &c2);
    __sincosf(4.0f * xi, &s4, &c4);
    __half2 p0 = __floats2half2_rn(xi, s1);
    __half2 p1 = __floats2half2_rn(s2, s4);
    __half2 p2 = __floats2half2_rn(c1, c2);
    __half2 p3 = __floats2half2_rn(c4, 1.0f);  // f7 = bias lane
    uint4 v = make_uint4(u32h2(p0), u32h2(p1), u32h2(p2), u32h2(p3));
    *reinterpret_cast<uint4*>(&g_feats_h[((size_t)i * B_ + b) * FP_]) = v;
}

// Kernel 2: block = (i-tile of 16, j), 128 threads (4 warps), 1024 blocks.
// occ 7 (one full wave, 72-reg budget for chain ILP).
//  - u = 0.5*(W1·feats + B1): m16n8k8 HMMA, fp16 accumulator
//  - silu: tanh.approx.f16x2 + HFMA2
//  - Σ_h s·W2: m16n8k16 HMMA, W2 replicated over n-cols, fp32 accumulator
// Epilogue: atomicAdd into out[b*J + j].
__global__ void __launch_bounds__(128, 7) kan_main_kernel(
    const float* __restrict__ W1,   // [I,J,H,7]
    const float* __restrict__ W2,   // [I,J,1,H]
    const float* __restrict__ B1,   // [I,J,H]
    const float* __restrict__ B2,   // [I,J,1]
    float* __restrict__ out)        // [B,J]
{
    __shared__ __align__(16) __half w1h[ITILE][H_][FP_];  // 0.5*W1, f7 = 0.5*B1
    __shared__ __align__(4)  __half w2h[ITILE][H_];       // W2 as half
    __shared__ float b2s[ITILE];

    const int j   = blockIdx.y;
    const int i0  = blockIdx.x * ITILE;
    const int tid = threadIdx.x;

    // Stage 0.5*W1 (branch-free; contiguous 224-float rows per il)
    for (int idx = tid; idx < ITILE * H_ * 7; idx += 128) {
        int il = idx / (H_ * 7);
        int r  = idx % (H_ * 7);          // r = h*7 + f
        size_t ij = (size_t)(i0 + il) * J_ + j;
        w1h[il][r / 7][r % 7] = __float2half(0.5f * W1[ij * (H_ * 7) + r]);
    }
    // Stage 0.5*B1 into f7 slot, W2 as half
    for (int idx = tid; idx < ITILE * H_; idx += 128) {
        int il = idx >> 5, h = idx & 31;
        size_t base = ((size_t)(i0 + il) * J_ + j) * H_ + h;
        w1h[il][h][7] = __float2half(0.5f * B1[base]);
        w2h[il][h]    = __float2half(W2[base]);
    }
    if (tid < ITILE) b2s[tid] = B2[(size_t)(i0 + tid) * J_ + j];
    __syncthreads();

    const int lane = tid & 31, warp = tid >> 5;
    const int gid = lane >> 2;      // fragment row selector
    const int tig = lane & 3;       // fragment col selector
    const int wbase = warp * 64;

    float bsum = 0.0f;
    #pragma unroll
    for (int il = 0; il < ITILE; il++) bsum += b2s[il];

    float acc[4][4] = {};           // [m-tile][k16-MMA D regs]
    const unsigned zero = 0;

    for (int il = 0; il < ITILE; il++) {
        const __half* fbase = g_feats_h + (size_t)(i0 + il) * (B_ * FP_);

        // A fragments for all 4 m-tiles (coalesced 128B lines, reused across hgp)
        unsigned A0[4], A1[4];
        #pragma unroll
        for (int mt = 0; mt < 4; mt++) {
            int brow = wbase + mt * 16 + gid;
            A0[mt] = *reinterpret_cast<const unsigned*>(fbase + brow * FP_ + tig * 2);
            A1[mt] = *reinterpret_cast<const unsigned*>(fbase + (brow + 8) * FP_ + tig * 2);
        }

        // W2 k16 B-fragments (il-dependent only; hoisted out of hgp loop)
        unsigned wb[4];
        #pragma unroll
        for (int q = 0; q < 4; q++)
            wb[q] = *reinterpret_cast<const unsigned*>(&w2h[il][q * 8 + tig * 2]);

        #pragma unroll
        for (int hgp = 0; hgp < 2; hgp++) {
            const int h0 = hgp * 16;
            unsigned wf0 = *reinterpret_cast<const unsigned*>(&w1h[il][h0 + gid][tig * 2]);
            unsigned wf1 = *reinterpret_cast<const unsigned*>(&w1h[il][h0 + 8 + gid][tig * 2]);
            unsigned wb0 = wb[hgp * 2], wb1 = wb[hgp * 2 + 1];

            #pragma unroll
            for (int mt = 0; mt < 4; mt++) {
                // u-MMA, fp16 accumulator: D regs are f16x2
                unsigned u0, u1, u2, u3;
                asm volatile(
                    "mma.sync.aligned.m16n8k8.row.col.f16.f16.f16.f16 "
                    "{%0,%1}, {%2,%3}, {%4}, {%5,%6};"
                    : "=r"(u0), "=r"(u1)
                    : "r"(A0[mt]), "r"(A1[mt]), "r"(wf0), "r"(zero), "r"(zero));
                asm volatile(
                    "mma.sync.aligned.m16n8k8.row.col.f16.f16.f16.f16 "
                    "{%0,%1}, {%2,%3}, {%4}, {%5,%6};"
                    : "=r"(u2), "=r"(u3)
                    : "r"(A0[mt]), "r"(A1[mt]), "r"(wf1), "r"(zero), "r"(zero));

                // silu(t) = u + u*tanh(u), u = t/2 — pure f16x2
                unsigned s0 = hfma2u(u0, tanh2u(u0), u0);
                unsigned s1 = hfma2u(u1, tanh2u(u1), u1);
                unsigned s2 = hfma2u(u2, tanh2u(u2), u2);
                unsigned s3 = hfma2u(u3, tanh2u(u3), u3);

                // h-contraction: m16n8k16, B = W2 replicated over n, fp32 acc
                asm volatile(
                    "mma.sync.aligned.m16n8k16.row.col.f32.f16.f16.f32 "
                    "{%0,%1,%2,%3}, {%4,%5,%6,%7}, {%8,%9}, {%0,%1,%2,%3};"
                    : "+f"(acc[mt][0]), "+f"(acc[mt][1]),
                      "+f"(acc[mt][2]), "+f"(acc[mt][3])
                    : "r"(s0), "r"(s1), "r"(s2), "r"(s3), "r"(wb0), "r"(wb1));
            }
        }
    }

    // Epilogue: tig==0 lanes hold per-b sums. Atomic-accumulate into out[b*J + j].
    if (tig == 0) {
        #pragma unroll
        for (int mt = 0; mt < 4; mt++) {
            int brow = wbase + mt * 16 + gid;
            atomicAdd(&out[(size_t)brow * J_ + j],       acc[mt][0] + bsum);
            atomicAdd(&out[(size_t)(brow + 8) * J_ + j], acc[mt][2] + bsum);
        }
    }
}

extern "C" void kernel_launch(void* const* d_in, const int* in_sizes, int n_in,
                              void* d_out, int out_size) {
    const float* x  = (const float*)d_in[0];
    const float* W1 = (const float*)d_in[1];
    const float* W2 = (const float*)d_in[2];
    const float* B1 = (const float*)d_in[3];
    const float* B2 = (const float*)d_in[4];
    float* out = (float*)d_out;

    feats_kernel<<<(B_ * I_) / 256, 256>>>(x, out);
    kan_main_kernel<<<dim3(IBLKS, J_), 128>>>(W1, W2, B1, B2, out);
}

// round 10
// speedup vs baseline: 1.2598x; 1.0434x over previous
#include <cuda_runtime.h>
#include <cuda_fp16.h>

// Problem constants
#define B_  256
#define I_  128
#define J_  128
#define H_  32
#define FP_ 8          // padded feature count; f7 = 1.0 bias lane
#define ITILE 16
#define IBLKS (I_ / ITILE)   // 8

// Scratch (allocation-free rule: __device__ globals)
__device__ __align__(16) __half g_feats_h[I_ * B_ * FP_];  // [i][b][f0..f7]

__device__ __forceinline__ unsigned u32h2(__half2 h) {
    return *reinterpret_cast<unsigned*>(&h);
}
__device__ __forceinline__ unsigned hfma2u(unsigned a, unsigned b, unsigned c) {
    unsigned d;
    asm("fma.rn.f16x2 %0, %1, %2, %3;" : "=r"(d) : "r"(a), "r"(b), "r"(c));
    return d;
}
__device__ __forceinline__ unsigned tanh2u(unsigned a) {
    unsigned d;
    asm("tanh.approx.f16x2 %0, %1;" : "=r"(d) : "r"(a));
    return d;
}

// Kernel 1: feats[i][b][8] = half{x, sin x, sin 2x, sin 4x, cos x, cos 2x, cos 4x, 1}
// Also zeroes out[t] (B*J == B*I == 32768 threads, exact cover).
// 256 blocks x 128 threads so all 148 SMs get work.
__global__ __launch_bounds__(128) void feats_kernel(const float* __restrict__ x,
                                                    float* __restrict__ out) {
    int t = blockIdx.x * 128 + threadIdx.x;   // t = b*I + i
    out[t] = 0.0f;
    int b = t >> 7, i = t & 127;
    float xi = x[t];                          // coalesced
    float s1, c1, s2, c2, s4, c4;
    __sincosf(xi, &s1, &c1);
    __sincosf(2.0f * xi, &s2, &c2);
    __sincosf(4.0f * xi, &s4, &c4);
    __half2 p0 = __floats2half2_rn(xi, s1);
    __half2 p1 = __floats2half2_rn(s2, s4);
    __half2 p2 = __floats2half2_rn(c1, c2);
    __half2 p3 = __floats2half2_rn(c4, 1.0f);  // f7 = bias lane
    uint4 v = make_uint4(u32h2(p0), u32h2(p1), u32h2(p2), u32h2(p3));
    *reinterpret_cast<uint4*>(&g_feats_h[((size_t)i * B_ + b) * FP_]) = v;
}

// Kernel 2: block = (i-tile of 16, j), 128 threads (4 warps), 1024 blocks,
// occ 8 (64-reg cap — measured-best operating point, R7).
//  - u = 0.5*(W1·feats + B1): m16n8k8 HMMA, fp16 accumulator
//  - silu: tanh.approx.f16x2 + HFMA2
//  - Σ_h s·W2: m16n8k16 HMMA, W2 replicated over n-cols, fp32 accumulator
// Epilogue: atomicAdd into out[b*J + j].
__global__ void __launch_bounds__(128, 8) kan_main_kernel(
    const float* __restrict__ W1,   // [I,J,H,7]
    const float* __restrict__ W2,   // [I,J,1,H]
    const float* __restrict__ B1,   // [I,J,H]
    const float* __restrict__ B2,   // [I,J,1]
    float* __restrict__ out)        // [B,J]
{
    __shared__ __align__(16) __half w1h[ITILE][H_][FP_];  // 0.5*W1, f7 = 0.5*B1
    __shared__ __align__(4)  __half w2h[ITILE][H_];       // W2 as half
    __shared__ float b2s[ITILE];

    const int j   = blockIdx.y;
    const int i0  = blockIdx.x * ITILE;
    const int tid = threadIdx.x;

    // Stage 0.5*W1 (branch-free; contiguous 224-float rows per il)
    for (int idx = tid; idx < ITILE * H_ * 7; idx += 128) {
        int il = idx / (H_ * 7);
        int r  = idx % (H_ * 7);          // r = h*7 + f
        size_t ij = (size_t)(i0 + il) * J_ + j;
        w1h[il][r / 7][r % 7] = __float2half(0.5f * W1[ij * (H_ * 7) + r]);
    }
    // Stage 0.5*B1 into f7 slot, W2 as half
    for (int idx = tid; idx < ITILE * H_; idx += 128) {
        int il = idx >> 5, h = idx & 31;
        size_t base = ((size_t)(i0 + il) * J_ + j) * H_ + h;
        w1h[il][h][7] = __float2half(0.5f * B1[base]);
        w2h[il][h]    = __float2half(W2[base]);
    }
    if (tid < ITILE) b2s[tid] = B2[(size_t)(i0 + tid) * J_ + j];
    __syncthreads();

    const int lane = tid & 31, warp = tid >> 5;
    const int gid = lane >> 2;      // fragment row selector
    const int tig = lane & 3;       // fragment col selector
    const int wbase = warp * 64;

    float bsum = 0.0f;
    #pragma unroll
    for (int il = 0; il < ITILE; il++) bsum += b2s[il];

    float acc[4][4] = {};           // [m-tile][k16-MMA D regs]
    const unsigned zero = 0;

    // Incremental feats pointer: one add per il instead of rederived addressing
    const __half* fbase = g_feats_h + (size_t)i0 * (B_ * FP_)
                        + (wbase + gid) * FP_ + tig * 2;

    for (int il = 0; il < ITILE; il++, fbase += B_ * FP_) {
        // A fragments for all 4 m-tiles (coalesced 128B lines, reused across hgp)
        unsigned A0[4], A1[4];
        #pragma unroll
        for (int mt = 0; mt < 4; mt++) {
            A0[mt] = *reinterpret_cast<const unsigned*>(fbase + mt * 16 * FP_);
            A1[mt] = *reinterpret_cast<const unsigned*>(fbase + (mt * 16 + 8) * FP_);
        }

        // W2 k16 B-fragments (il-dependent only; hoisted out of hgp loop)
        unsigned wb[4];
        #pragma unroll
        for (int q = 0; q < 4; q++)
            wb[q] = *reinterpret_cast<const unsigned*>(&w2h[il][q * 8 + tig * 2]);

        #pragma unroll
        for (int hgp = 0; hgp < 2; hgp++) {
            const int h0 = hgp * 16;
            unsigned wf0 = *reinterpret_cast<const unsigned*>(&w1h[il][h0 + gid][tig * 2]);
            unsigned wf1 = *reinterpret_cast<const unsigned*>(&w1h[il][h0 + 8 + gid][tig * 2]);
            unsigned wb0 = wb[hgp * 2], wb1 = wb[hgp * 2 + 1];

            #pragma unroll
            for (int mt = 0; mt < 4; mt++) {
                // u-MMA, fp16 accumulator: D regs are f16x2
                unsigned u0, u1, u2, u3;
                asm volatile(
                    "mma.sync.aligned.m16n8k8.row.col.f16.f16.f16.f16 "
                    "{%0,%1}, {%2,%3}, {%4}, {%5,%6};"
                    : "=r"(u0), "=r"(u1)
                    : "r"(A0[mt]), "r"(A1[mt]), "r"(wf0), "r"(zero), "r"(zero));
                asm volatile(
                    "mma.sync.aligned.m16n8k8.row.col.f16.f16.f16.f16 "
                    "{%0,%1}, {%2,%3}, {%4}, {%5,%6};"
                    : "=r"(u2), "=r"(u3)
                    : "r"(A0[mt]), "r"(A1[mt]), "r"(wf1), "r"(zero), "r"(zero));

                // silu(t) = u + u*tanh(u), u = t/2 — pure f16x2
                unsigned s0 = hfma2u(u0, tanh2u(u0), u0);
                unsigned s1 = hfma2u(u1, tanh2u(u1), u1);
                unsigned s2 = hfma2u(u2, tanh2u(u2), u2);
                unsigned s3 = hfma2u(u3, tanh2u(u3), u3);

                // h-contraction: m16n8k16, B = W2 replicated over n, fp32 acc
                asm volatile(
                    "mma.sync.aligned.m16n8k16.row.col.f32.f16.f16.f32 "
                    "{%0,%1,%2,%3}, {%4,%5,%6,%7}, {%8,%9}, {%0,%1,%2,%3};"
                    : "+f"(acc[mt][0]), "+f"(acc[mt][1]),
                      "+f"(acc[mt][2]), "+f"(acc[mt][3])
                    : "r"(s0), "r"(s1), "r"(s2), "r"(s3), "r"(wb0), "r"(wb1));
            }
        }
    }

    // Epilogue: tig==0 lanes hold per-b sums. Atomic-accumulate into out[b*J + j].
    if (tig == 0) {
        #pragma unroll
        for (int mt = 0; mt < 4; mt++) {
            int brow = wbase + mt * 16 + gid;
            atomicAdd(&out[(size_t)brow * J_ + j],       acc[mt][0] + bsum);
            atomicAdd(&out[(size_t)(brow + 8) * J_ + j], acc[mt][2] + bsum);
        }
    }
}

extern "C" void kernel_launch(void* const* d_in, const int* in_sizes, int n_in,
                              void* d_out, int out_size) {
    const float* x  = (const float*)d_in[0];
    const float* W1 = (const float*)d_in[1];
    const float* W2 = (const float*)d_in[2];
    const float* B1 = (const float*)d_in[3];
    const float* B2 = (const float*)d_in[4];
    float* out = (float*)d_out;

    feats_kernel<<<(B_ * I_) / 128, 128>>>(x, out);
    kan_main_kernel<<<dim3(IBLKS, J_), 128>>>(W1, W2, B1, B2, out);
}

// round 11
// speedup vs baseline: 1.3180x; 1.0461x over previous
#include <cuda_runtime.h>
#include <cuda_fp16.h>

// Problem constants
#define B_  256
#define I_  128
#define J_  128
#define H_  32
#define FP_ 8          // padded feature count; f7 = 1.0 bias lane
#define ITILE 16
#define IBLKS (I_ / ITILE)   // 8

// Scratch (allocation-free rule: __device__ globals)
__device__ __align__(16) __half g_feats_h[I_ * B_ * FP_];  // [i][b][f0..f7]

__device__ __forceinline__ unsigned u32h2(__half2 h) {
    return *reinterpret_cast<unsigned*>(&h);
}
__device__ __forceinline__ unsigned hfma2u(unsigned a, unsigned b, unsigned c) {
    unsigned d;
    asm("fma.rn.f16x2 %0, %1, %2, %3;" : "=r"(d) : "r"(a), "r"(b), "r"(c));
    return d;
}
__device__ __forceinline__ unsigned tanh2u(unsigned a) {
    unsigned d;
    asm("tanh.approx.f16x2 %0, %1;" : "=r"(d) : "r"(a));
    return d;
}

// Kernel 1: feats[i][b][8] = half{x, sin x, sin 2x, sin 4x, cos x, cos 2x, cos 4x, 1}
// Also zeroes out[t] (B*J == B*I == 32768 threads, exact cover).
__global__ __launch_bounds__(128) void feats_kernel(const float* __restrict__ x,
                                                    float* __restrict__ out) {
    int t = blockIdx.x * 128 + threadIdx.x;   // t = b*I + i
    out[t] = 0.0f;
    int b = t >> 7, i = t & 127;
    float xi = x[t];                          // coalesced
    float s1, c1, s2, c2, s4, c4;
    __sincosf(xi, &s1, &c1);
    __sincosf(2.0f * xi, &s2, &c2);
    __sincosf(4.0f * xi, &s4, &c4);
    __half2 p0 = __floats2half2_rn(xi, s1);
    __half2 p1 = __floats2half2_rn(s2, s4);
    __half2 p2 = __floats2half2_rn(c1, c2);
    __half2 p3 = __floats2half2_rn(c4, 1.0f);  // f7 = bias lane
    uint4 v = make_uint4(u32h2(p0), u32h2(p1), u32h2(p2), u32h2(p3));
    *reinterpret_cast<uint4*>(&g_feats_h[((size_t)i * B_ + b) * FP_]) = v;
}

// Kernel 2: block = (i-tile of 16, j), 128 threads (4 warps), 1024 blocks, occ 8.
// Fragment-packed smem:
//   w1p[il][gid][tig] : uint4 whose q-th u32 = half2(0.5*W1[i,j,h=q*8+gid, f=tig*2],
//                                                    0.5*W1[... f=tig*2+1])  (f7 -> 0.5*B1)
//   w2p[il][tig]      : uint4 whose q-th u32 = half2(W2[h=q*8+tig*2], W2[h+1])
// One LDS.128 each per il replaces 6 scalar LDS + address math.
// A-fragments (gmem) prefetched one il ahead to hide L2 latency.
__global__ void __launch_bounds__(128, 8) kan_main_kernel(
    const float* __restrict__ W1,   // [I,J,H,7]
    const float* __restrict__ W2,   // [I,J,1,H]
    const float* __restrict__ B1,   // [I,J,H]
    const float* __restrict__ B2,   // [I,J,1]
    float* __restrict__ out)        // [B,J]
{
    __shared__ __align__(16) uint4 w1p[ITILE][8][4];  // [il][gid][tig]
    __shared__ __align__(16) uint4 w2p[ITILE][4];     // [il][tig]
    __shared__ float b2s[ITILE];

    const int j   = blockIdx.y;
    const int i0  = blockIdx.x * ITILE;
    const int tid = threadIdx.x;

    // Stage W1/B1 as packed fragments (2048 half2 values, 16 iters)
    {
        unsigned* w1u = reinterpret_cast<unsigned*>(w1p);
        for (int idx = tid; idx < ITILE * 32 * 4; idx += 128) {
            int il = idx >> 7;
            int r  = idx & 127;
            int h  = r >> 2;
            int p  = r & 3;
            size_t ij = (size_t)(i0 + il) * J_ + j;
            const float* w1row = W1 + ij * (H_ * 7) + h * 7;
            float lo = 0.5f * w1row[2 * p];
            float hi = 0.5f * ((p < 3) ? w1row[2 * p + 1] : B1[ij * H_ + h]);
            w1u[il * 128 + (h & 7) * 16 + p * 4 + (h >> 3)] =
                u32h2(__floats2half2_rn(lo, hi));
        }
    }
    // Stage W2 as packed fragments (256 half2 values)
    {
        unsigned* w2u = reinterpret_cast<unsigned*>(w2p);
        for (int idx = tid; idx < ITILE * 16; idx += 128) {
            int il = idx >> 4;
            int r  = idx & 15;
            int tg = r >> 2;
            int q  = r & 3;
            int h  = q * 8 + tg * 2;
            const float* w2row = W2 + ((size_t)(i0 + il) * J_ + j) * H_;
            w2u[il * 16 + tg * 4 + q] =
                u32h2(__floats2half2_rn(w2row[h], w2row[h + 1]));
        }
    }
    if (tid < ITILE) b2s[tid] = B2[(size_t)(i0 + tid) * J_ + j];
    __syncthreads();

    const int lane = tid & 31, warp = tid >> 5;
    const int gid = lane >> 2;      // fragment row selector
    const int tig = lane & 3;       // fragment col selector
    const int wbase = warp * 64;

    float bsum = 0.0f;
    #pragma unroll
    for (int il = 0; il < ITILE; il++) bsum += b2s[il];

    float acc[4][4] = {};           // [m-tile][k16-MMA D regs]
    const unsigned zero = 0;

    const __half* fbase = g_feats_h + (size_t)i0 * (B_ * FP_)
                        + (wbase + gid) * FP_ + tig * 2;

    // Prefetch il=0 A-fragments
    unsigned A0[4], A1[4];
    #pragma unroll
    for (int mt = 0; mt < 4; mt++) {
        A0[mt] = *reinterpret_cast<const unsigned*>(fbase + mt * 16 * FP_);
        A1[mt] = *reinterpret_cast<const unsigned*>(fbase + (mt * 16 + 8) * FP_);
    }

    #pragma unroll
    for (int il = 0; il < ITILE; il++) {
        // Prefetch next il's A-fragments (L2 latency overlapped with compute)
        unsigned N0[4], N1[4];
        if (il + 1 < ITILE) {
            const __half* fn = fbase + (il + 1) * (B_ * FP_);
            #pragma unroll
            for (int mt = 0; mt < 4; mt++) {
                N0[mt] = *reinterpret_cast<const unsigned*>(fn + mt * 16 * FP_);
                N1[mt] = *reinterpret_cast<const unsigned*>(fn + (mt * 16 + 8) * FP_);
            }
        }

        // One LDS.128 each: all W1 fragments (wq) and W2 fragments (bq) for this il
        uint4 wq = w1p[il][gid][tig];   // x,y,z,w = wf for h-groups 0..3
        uint4 bq = w2p[il][tig];        // x,y,z,w = wb for h-groups 0..3

        #pragma unroll
        for (int hgp = 0; hgp < 2; hgp++) {
            unsigned wf0 = hgp ? wq.z : wq.x;
            unsigned wf1 = hgp ? wq.w : wq.y;
            unsigned wb0 = hgp ? bq.z : bq.x;
            unsigned wb1 = hgp ? bq.w : bq.y;

            #pragma unroll
            for (int mt = 0; mt < 4; mt++) {
                // u-MMA, fp16 accumulator: D regs are f16x2
                unsigned u0, u1, u2, u3;
                asm volatile(
                    "mma.sync.aligned.m16n8k8.row.col.f16.f16.f16.f16 "
                    "{%0,%1}, {%2,%3}, {%4}, {%5,%6};"
                    : "=r"(u0), "=r"(u1)
                    : "r"(A0[mt]), "r"(A1[mt]), "r"(wf0), "r"(zero), "r"(zero));
                asm volatile(
                    "mma.sync.aligned.m16n8k8.row.col.f16.f16.f16.f16 "
                    "{%0,%1}, {%2,%3}, {%4}, {%5,%6};"
                    : "=r"(u2), "=r"(u3)
                    : "r"(A0[mt]), "r"(A1[mt]), "r"(wf1), "r"(zero), "r"(zero));

                // silu(t) = u + u*tanh(u), u = t/2 — pure f16x2
                unsigned s0 = hfma2u(u0, tanh2u(u0), u0);
                unsigned s1 = hfma2u(u1, tanh2u(u1), u1);
                unsigned s2 = hfma2u(u2, tanh2u(u2), u2);
                unsigned s3 = hfma2u(u3, tanh2u(u3), u3);

                // h-contraction: m16n8k16, B = W2 replicated over n, fp32 acc
                asm volatile(
                    "mma.sync.aligned.m16n8k16.row.col.f32.f16.f16.f32 "
                    "{%0,%1,%2,%3}, {%4,%5,%6,%7}, {%8,%9}, {%0,%1,%2,%3};"
                    : "+f"(acc[mt][0]), "+f"(acc[mt][1]),
                      "+f"(acc[mt][2]), "+f"(acc[mt][3])
                    : "r"(s0), "r"(s1), "r"(s2), "r"(s3), "r"(wb0), "r"(wb1));
            }
        }

        // Rotate prefetch buffers
        #pragma unroll
        for (int mt = 0; mt < 4; mt++) { A0[mt] = N0[mt]; A1[mt] = N1[mt]; }
    }

    // Epilogue: tig==0 lanes hold per-b sums. Atomic-accumulate into out[b*J + j].
    if (tig == 0) {
        #pragma unroll
        for (int mt = 0; mt < 4; mt++) {
            int brow = wbase + mt * 16 + gid;
            atomicAdd(&out[(size_t)brow * J_ + j],       acc[mt][0] + bsum);
            atomicAdd(&out[(size_t)(brow + 8) * J_ + j], acc[mt][2] + bsum);
        }
    }
}

extern "C" void kernel_launch(void* const* d_in, const int* in_sizes, int n_in,
                              void* d_out, int out_size) {
    const float* x  = (const float*)d_in[0];
    const float* W1 = (const float*)d_in[1];
    const float* W2 = (const float*)d_in[2];
    const float* B1 = (const float*)d_in[3];
    const float* B2 = (const float*)d_in[4];
    float* out = (float*)d_out;

    feats_kernel<<<(B_ * I_) / 128, 128>>>(x, out);
    kan_main_kernel<<<dim3(IBLKS, J_), 128>>>(W1, W2, B1, B2, out);
}

// round 12
// speedup vs baseline: 1.3505x; 1.0247x over previous
#include <cuda_runtime.h>
#include <cuda_fp16.h>

// Problem constants
#define B_  256
#define I_  128
#define J_  128
#define H_  32
#define FP_ 8          // padded feature count; f7 = 1.0 bias lane
#define ITILE 8
#define IBLKS (I_ / ITILE)   // 16

// Scratch (allocation-free rule: __device__ globals)
__device__ __align__(16) __half g_feats_h[I_ * B_ * FP_];  // [i][b][f0..f7]

__device__ __forceinline__ unsigned u32h2(__half2 h) {
    return *reinterpret_cast<unsigned*>(&h);
}
__device__ __forceinline__ unsigned hfma2u(unsigned a, unsigned b, unsigned c) {
    unsigned d;
    asm("fma.rn.f16x2 %0, %1, %2, %3;" : "=r"(d) : "r"(a), "r"(b), "r"(c));
    return d;
}
__device__ __forceinline__ unsigned tanh2u(unsigned a) {
    unsigned d;
    asm("tanh.approx.f16x2 %0, %1;" : "=r"(d) : "r"(a));
    return d;
}

// Kernel 1: feats[i][b][8] = half{x, sin x, sin 2x, sin 4x, cos x, cos 2x, cos 4x, 1}
// Also zeroes out[t] (B*J == B*I == 32768 threads, exact cover).
__global__ __launch_bounds__(128) void feats_kernel(const float* __restrict__ x,
                                                    float* __restrict__ out) {
    int t = blockIdx.x * 128 + threadIdx.x;   // t = b*I + i
    out[t] = 0.0f;
    int b = t >> 7, i = t & 127;
    float xi = x[t];                          // coalesced
    float s1, c1, s2, c2, s4, c4;
    __sincosf(xi, &s1, &c1);
    __sincosf(2.0f * xi, &s2, &c2);
    __sincosf(4.0f * xi, &s4, &c4);
    __half2 p0 = __floats2half2_rn(xi, s1);
    __half2 p1 = __floats2half2_rn(s2, s4);
    __half2 p2 = __floats2half2_rn(c1, c2);
    __half2 p3 = __floats2half2_rn(c4, 1.0f);  // f7 = bias lane
    uint4 v = make_uint4(u32h2(p0), u32h2(p1), u32h2(p2), u32h2(p3));
    *reinterpret_cast<uint4*>(&g_feats_h[((size_t)i * B_ + b) * FP_]) = v;
}

// Kernel 2: block = (i-tile of 8, j), 128 threads (4 warps), 2048 blocks.
// 48-reg cap (occ 10) -> ~40 warps/SM for latency hiding.
// Fragment-packed smem (one LDS.128 per operand class per il):
//   w1p[il][gid][tig] : uint4, q-th u32 = half2(0.5*W1[h=q*8+gid, f=tig*2..+1]), f7->0.5*B1
//   w2p[il][tig]      : uint4, q-th u32 = half2(W2[h=q*8+tig*2], W2[h+1])
__global__ void __launch_bounds__(128, 10) kan_main_kernel(
    const float* __restrict__ W1,   // [I,J,H,7]
    const float* __restrict__ W2,   // [I,J,1,H]
    const float* __restrict__ B1,   // [I,J,H]
    const float* __restrict__ B2,   // [I,J,1]
    float* __restrict__ out)        // [B,J]
{
    __shared__ __align__(16) uint4 w1p[ITILE][8][4];  // [il][gid][tig]
    __shared__ __align__(16) uint4 w2p[ITILE][4];     // [il][tig]
    __shared__ float b2s[ITILE];

    const int j   = blockIdx.y;
    const int i0  = blockIdx.x * ITILE;
    const int tid = threadIdx.x;

    // Stage W1/B1 as packed fragments
    {
        unsigned* w1u = reinterpret_cast<unsigned*>(w1p);
        for (int idx = tid; idx < ITILE * 32 * 4; idx += 128) {
            int il = idx >> 7;
            int r  = idx & 127;
            int h  = r >> 2;
            int p  = r & 3;
            size_t ij = (size_t)(i0 + il) * J_ + j;
            const float* w1row = W1 + ij * (H_ * 7) + h * 7;
            float lo = 0.5f * w1row[2 * p];
            float hi = 0.5f * ((p < 3) ? w1row[2 * p + 1] : B1[ij * H_ + h]);
            w1u[il * 128 + (h & 7) * 16 + p * 4 + (h >> 3)] =
                u32h2(__floats2half2_rn(lo, hi));
        }
    }
    // Stage W2 as packed fragments
    {
        unsigned* w2u = reinterpret_cast<unsigned*>(w2p);
        for (int idx = tid; idx < ITILE * 16; idx += 128) {
            int il = idx >> 4;
            int r  = idx & 15;
            int tg = r >> 2;
            int q  = r & 3;
            int h  = q * 8 + tg * 2;
            const float* w2row = W2 + ((size_t)(i0 + il) * J_ + j) * H_;
            w2u[il * 16 + tg * 4 + q] =
                u32h2(__floats2half2_rn(w2row[h], w2row[h + 1]));
        }
    }
    if (tid < ITILE) b2s[tid] = B2[(size_t)(i0 + tid) * J_ + j];
    __syncthreads();

    const int lane = tid & 31, warp = tid >> 5;
    const int gid = lane >> 2;      // fragment row selector
    const int tig = lane & 3;       // fragment col selector
    const int wbase = warp * 64;

    float bsum = 0.0f;
    #pragma unroll
    for (int il = 0; il < ITILE; il++) bsum += b2s[il];

    float acc[4][4] = {};           // [m-tile][k16-MMA D regs]
    const unsigned zero = 0;

    const __half* fbase = g_feats_h + (size_t)i0 * (B_ * FP_)
                        + (wbase + gid) * FP_ + tig * 2;

    #pragma unroll
    for (int il = 0; il < ITILE; il++) {
        // A fragments for all 4 m-tiles (coalesced; L2/L1-hot across j-blocks)
        const __half* fi = fbase + il * (B_ * FP_);
        unsigned A0[4], A1[4];
        #pragma unroll
        for (int mt = 0; mt < 4; mt++) {
            A0[mt] = *reinterpret_cast<const unsigned*>(fi + mt * 16 * FP_);
            A1[mt] = *reinterpret_cast<const unsigned*>(fi + (mt * 16 + 8) * FP_);
        }

        // One LDS.128 each: all W1 fragments (wq) and W2 fragments (bq) for this il
        uint4 wq = w1p[il][gid][tig];   // x,y,z,w = wf for h-groups 0..3
        uint4 bq = w2p[il][tig];        // x,y,z,w = wb for h-groups 0..3

        #pragma unroll
        for (int hgp = 0; hgp < 2; hgp++) {
            unsigned wf0 = hgp ? wq.z : wq.x;
            unsigned wf1 = hgp ? wq.w : wq.y;
            unsigned wb0 = hgp ? bq.z : bq.x;
            unsigned wb1 = hgp ? bq.w : bq.y;

            #pragma unroll
            for (int mt = 0; mt < 4; mt++) {
                // u-MMA, fp16 accumulator: D regs are f16x2
                unsigned u0, u1, u2, u3;
                asm volatile(
                    "mma.sync.aligned.m16n8k8.row.col.f16.f16.f16.f16 "
                    "{%0,%1}, {%2,%3}, {%4}, {%5,%6};"
                    : "=r"(u0), "=r"(u1)
                    : "r"(A0[mt]), "r"(A1[mt]), "r"(wf0), "r"(zero), "r"(zero));
                asm volatile(
                    "mma.sync.aligned.m16n8k8.row.col.f16.f16.f16.f16 "
                    "{%0,%1}, {%2,%3}, {%4}, {%5,%6};"
                    : "=r"(u2), "=r"(u3)
                    : "r"(A0[mt]), "r"(A1[mt]), "r"(wf1), "r"(zero), "r"(zero));

                // silu(t) = u + u*tanh(u), u = t/2 — pure f16x2
                unsigned s0 = hfma2u(u0, tanh2u(u0), u0);
                unsigned s1 = hfma2u(u1, tanh2u(u1), u1);
                unsigned s2 = hfma2u(u2, tanh2u(u2), u2);
                unsigned s3 = hfma2u(u3, tanh2u(u3), u3);

                // h-contraction: m16n8k16, B = W2 replicated over n, fp32 acc
                asm volatile(
                    "mma.sync.aligned.m16n8k16.row.col.f32.f16.f16.f32 "
                    "{%0,%1,%2,%3}, {%4,%5,%6,%7}, {%8,%9}, {%0,%1,%2,%3};"
                    : "+f"(acc[mt][0]), "+f"(acc[mt][1]),
                      "+f"(acc[mt][2]), "+f"(acc[mt][3])
                    : "r"(s0), "r"(s1), "r"(s2), "r"(s3), "r"(wb0), "r"(wb1));
            }
        }
    }

    // Epilogue: tig==0 lanes hold per-b sums. Atomic-accumulate into out[b*J + j].
    if (tig == 0) {
        #pragma unroll
        for (int mt = 0; mt < 4; mt++) {
            int brow = wbase + mt * 16 + gid;
            atomicAdd(&out[(size_t)brow * J_ + j],       acc[mt][0] + bsum);
            atomicAdd(&out[(size_t)(brow + 8) * J_ + j], acc[mt][2] + bsum);
        }
    }
}

extern "C" void kernel_launch(void* const* d_in, const int* in_sizes, int n_in,
                              void* d_out, int out_size) {
    const float* x  = (const float*)d_in[0];
    const float* W1 = (const float*)d_in[1];
    const float* W2 = (const float*)d_in[2];
    const float* B1 = (const float*)d_in[3];
    const float* B2 = (const float*)d_in[4];
    float* out = (float*)d_out;

    feats_kernel<<<(B_ * I_) / 128, 128>>>(x, out);
    kan_main_kernel<<<dim3(IBLKS, J_), 128>>>(W1, W2, B1, B2, out);
}

// round 13
// speedup vs baseline: 1.3807x; 1.0223x over previous
#include <cuda_runtime.h>
#include <cuda_fp16.h>

// Problem constants
#define B_  256
#define I_  128
#define J_  128
#define H_  32
#define FP_ 8          // padded feature count; f7 = 1.0 bias lane
#define ITILE 4
#define IBLKS (I_ / ITILE)   // 32

// Scratch (allocation-free rule: __device__ globals)
__device__ __align__(16) __half g_feats_h[I_ * B_ * FP_];  // [i][b][f0..f7]

__device__ __forceinline__ unsigned u32h2(__half2 h) {
    return *reinterpret_cast<unsigned*>(&h);
}
__device__ __forceinline__ unsigned hfma2u(unsigned a, unsigned b, unsigned c) {
    unsigned d;
    asm("fma.rn.f16x2 %0, %1, %2, %3;" : "=r"(d) : "r"(a), "r"(b), "r"(c));
    return d;
}
__device__ __forceinline__ unsigned tanh2u(unsigned a) {
    unsigned d;
    asm("tanh.approx.f16x2 %0, %1;" : "=r"(d) : "r"(a));
    return d;
}

// Kernel 1: feats[i][b][8] = half{x, sin x, sin 2x, sin 4x, cos x, cos 2x, cos 4x, 1}
// Also zeroes out[t] (B*J == B*I == 32768 threads, exact cover).
__global__ __launch_bounds__(128) void feats_kernel(const float* __restrict__ x,
                                                    float* __restrict__ out) {
    int t = blockIdx.x * 128 + threadIdx.x;   // t = b*I + i
    out[t] = 0.0f;
    int b = t >> 7, i = t & 127;
    float xi = x[t];                          // coalesced
    float s1, c1, s2, c2, s4, c4;
    __sincosf(xi, &s1, &c1);
    __sincosf(2.0f * xi, &s2, &c2);
    __sincosf(4.0f * xi, &s4, &c4);
    __half2 p0 = __floats2half2_rn(xi, s1);
    __half2 p1 = __floats2half2_rn(s2, s4);
    __half2 p2 = __floats2half2_rn(c1, c2);
    __half2 p3 = __floats2half2_rn(c4, 1.0f);  // f7 = bias lane
    uint4 v = make_uint4(u32h2(p0), u32h2(p1), u32h2(p2), u32h2(p3));
    *reinterpret_cast<uint4*>(&g_feats_h[((size_t)i * B_ + b) * FP_]) = v;
}

// Kernel 2: block = (i-tile of 4, j), 128 threads (4 warps), 4096 blocks.
// 48-reg cap (occ 10). Small block quantum -> 2.77 blocks/slot -> low makespan
// quantization (vs 1.38 at ITILE=8 which cost ~45%).
// Fragment-packed smem (one LDS.128 per operand class per il):
//   w1p[il][gid][tig] : uint4, q-th u32 = half2(0.5*W1[h=q*8+gid, f=tig*2..+1]), f7->0.5*B1
//   w2p[il][tig]      : uint4, q-th u32 = half2(W2[h=q*8+tig*2], W2[h+1])
__global__ void __launch_bounds__(128, 10) kan_main_kernel(
    const float* __restrict__ W1,   // [I,J,H,7]
    const float* __restrict__ W2,   // [I,J,1,H]
    const float* __restrict__ B1,   // [I,J,H]
    const float* __restrict__ B2,   // [I,J,1]
    float* __restrict__ out)        // [B,J]
{
    __shared__ __align__(16) uint4 w1p[ITILE][8][4];  // [il][gid][tig]
    __shared__ __align__(16) uint4 w2p[ITILE][4];     // [il][tig]
    __shared__ float b2s[ITILE];

    const int j   = blockIdx.y;
    const int i0  = blockIdx.x * ITILE;
    const int tid = threadIdx.x;

    // Stage W1/B1 as packed fragments (ITILE*128 u32 writes)
    {
        unsigned* w1u = reinterpret_cast<unsigned*>(w1p);
        for (int idx = tid; idx < ITILE * 32 * 4; idx += 128) {
            int il = idx >> 7;
            int r  = idx & 127;
            int h  = r >> 2;
            int p  = r & 3;
            size_t ij = (size_t)(i0 + il) * J_ + j;
            const float* w1row = W1 + ij * (H_ * 7) + h * 7;
            float lo = 0.5f * w1row[2 * p];
            float hi = 0.5f * ((p < 3) ? w1row[2 * p + 1] : B1[ij * H_ + h]);
            w1u[il * 128 + (h & 7) * 16 + p * 4 + (h >> 3)] =
                u32h2(__floats2half2_rn(lo, hi));
        }
    }
    // Stage W2 as packed fragments
    {
        unsigned* w2u = reinterpret_cast<unsigned*>(w2p);
        for (int idx = tid; idx < ITILE * 16; idx += 128) {
            int il = idx >> 4;
            int r  = idx & 15;
            int tg = r >> 2;
            int q  = r & 3;
            int h  = q * 8 + tg * 2;
            const float* w2row = W2 + ((size_t)(i0 + il) * J_ + j) * H_;
            w2u[il * 16 + tg * 4 + q] =
                u32h2(__floats2half2_rn(w2row[h], w2row[h + 1]));
        }
    }
    if (tid < ITILE) b2s[tid] = B2[(size_t)(i0 + tid) * J_ + j];
    __syncthreads();

    const int lane = tid & 31, warp = tid >> 5;
    const int gid = lane >> 2;      // fragment row selector
    const int tig = lane & 3;       // fragment col selector
    const int wbase = warp * 64;

    float bsum = 0.0f;
    #pragma unroll
    for (int il = 0; il < ITILE; il++) bsum += b2s[il];

    float acc[4][4] = {};           // [m-tile][k16-MMA D regs]
    const unsigned zero = 0;

    const __half* fbase = g_feats_h + (size_t)i0 * (B_ * FP_)
                        + (wbase + gid) * FP_ + tig * 2;

    #pragma unroll
    for (int il = 0; il < ITILE; il++) {
        // A fragments for all 4 m-tiles (coalesced; L2-hot across j-blocks)
        const __half* fi = fbase + il * (B_ * FP_);
        unsigned A0[4], A1[4];
        #pragma unroll
        for (int mt = 0; mt < 4; mt++) {
            A0[mt] = *reinterpret_cast<const unsigned*>(fi + mt * 16 * FP_);
            A1[mt] = *reinterpret_cast<const unsigned*>(fi + (mt * 16 + 8) * FP_);
        }

        // One LDS.128 each: all W1 fragments (wq) and W2 fragments (bq) for this il
        uint4 wq = w1p[il][gid][tig];   // x,y,z,w = wf for h-groups 0..3
        uint4 bq = w2p[il][tig];        // x,y,z,w = wb for h-groups 0..3

        #pragma unroll
        for (int hgp = 0; hgp < 2; hgp++) {
            unsigned wf0 = hgp ? wq.z : wq.x;
            unsigned wf1 = hgp ? wq.w : wq.y;
            unsigned wb0 = hgp ? bq.z : bq.x;
            unsigned wb1 = hgp ? bq.w : bq.y;

            #pragma unroll
            for (int mt = 0; mt < 4; mt++) {
                // u-MMA, fp16 accumulator: D regs are f16x2
                unsigned u0, u1, u2, u3;
                asm volatile(
                    "mma.sync.aligned.m16n8k8.row.col.f16.f16.f16.f16 "
                    "{%0,%1}, {%2,%3}, {%4}, {%5,%6};"
                    : "=r"(u0), "=r"(u1)
                    : "r"(A0[mt]), "r"(A1[mt]), "r"(wf0), "r"(zero), "r"(zero));
                asm volatile(
                    "mma.sync.aligned.m16n8k8.row.col.f16.f16.f16.f16 "
                    "{%0,%1}, {%2,%3}, {%4}, {%5,%6};"
                    : "=r"(u2), "=r"(u3)
                    : "r"(A0[mt]), "r"(A1[mt]), "r"(wf1), "r"(zero), "r"(zero));

                // silu(t) = u + u*tanh(u), u = t/2 — pure f16x2
                unsigned s0 = hfma2u(u0, tanh2u(u0), u0);
                unsigned s1 = hfma2u(u1, tanh2u(u1), u1);
                unsigned s2 = hfma2u(u2, tanh2u(u2), u2);
                unsigned s3 = hfma2u(u3, tanh2u(u3), u3);

                // h-contraction: m16n8k16, B = W2 replicated over n, fp32 acc
                asm volatile(
                    "mma.sync.aligned.m16n8k16.row.col.f32.f16.f16.f32 "
                    "{%0,%1,%2,%3}, {%4,%5,%6,%7}, {%8,%9}, {%0,%1,%2,%3};"
                    : "+f"(acc[mt][0]), "+f"(acc[mt][1]),
                      "+f"(acc[mt][2]), "+f"(acc[mt][3])
                    : "r"(s0), "r"(s1), "r"(s2), "r"(s3), "r"(wb0), "r"(wb1));
            }
        }
    }

    // Epilogue: tig==0 lanes hold per-b sums. Atomic-accumulate into out[b*J + j].
    if (tig == 0) {
        #pragma unroll
        for (int mt = 0; mt < 4; mt++) {
            int brow = wbase + mt * 16 + gid;
            atomicAdd(&out[(size_t)brow * J_ + j],       acc[mt][0] + bsum);
            atomicAdd(&out[(size_t)(brow + 8) * J_ + j], acc[mt][2] + bsum);
        }
    }
}

extern "C" void kernel_launch(void* const* d_in, const int* in_sizes, int n_in,
                              void* d_out, int out_size) {
    const float* x  = (const float*)d_in[0];
    const float* W1 = (const float*)d_in[1];
    const float* W2 = (const float*)d_in[2];
    const float* B1 = (const float*)d_in[3];
    const float* B2 = (const float*)d_in[4];
    float* out = (float*)d_out;

    feats_kernel<<<(B_ * I_) / 128, 128>>>(x, out);
    kan_main_kernel<<<dim3(IBLKS, J_), 128>>>(W1, W2, B1, B2, out);
}

// round 14
// speedup vs baseline: 1.4451x; 1.0467x over previous
#include <cuda_runtime.h>
#include <cuda_fp16.h>

// Problem constants
#define B_  256
#define I_  128
#define J_  128
#define H_  32
#define FP_ 8          // padded feature count; f7 = 1.0 bias lane
#define ITILE 4
#define IBLKS (I_ / ITILE)   // 32

// Scratch (allocation-free rule: __device__ globals)
__device__ __align__(16) __half g_feats_h[I_ * B_ * FP_];  // [i][b][f0..f7]

__device__ __forceinline__ unsigned u32h2(__half2 h) {
    return *reinterpret_cast<unsigned*>(&h);
}
__device__ __forceinline__ unsigned hfma2u(unsigned a, unsigned b, unsigned c) {
    unsigned d;
    asm("fma.rn.f16x2 %0, %1, %2, %3;" : "=r"(d) : "r"(a), "r"(b), "r"(c));
    return d;
}
__device__ __forceinline__ unsigned tanh2u(unsigned a) {
    unsigned d;
    asm("tanh.approx.f16x2 %0, %1;" : "=r"(d) : "r"(a));
    return d;
}

// Kernel 1: feats[i][b][8] = half{x, sin x, sin 2x, sin 4x, cos x, cos 2x, cos 4x, 1}
// Also zeroes out[t] (B*J == B*I == 32768 threads, exact cover).
__global__ __launch_bounds__(128) void feats_kernel(const float* __restrict__ x,
                                                    float* __restrict__ out) {
    int t = blockIdx.x * 128 + threadIdx.x;   // t = b*I + i
    out[t] = 0.0f;
    int b = t >> 7, i = t & 127;
    float xi = x[t];                          // coalesced
    float s1, c1, s2, c2, s4, c4;
    __sincosf(xi, &s1, &c1);
    __sincosf(2.0f * xi, &s2, &c2);
    __sincosf(4.0f * xi, &s4, &c4);
    __half2 p0 = __floats2half2_rn(xi, s1);
    __half2 p1 = __floats2half2_rn(s2, s4);
    __half2 p2 = __floats2half2_rn(c1, c2);
    __half2 p3 = __floats2half2_rn(c4, 1.0f);  // f7 = bias lane
    uint4 v = make_uint4(u32h2(p0), u32h2(p1), u32h2(p2), u32h2(p3));
    *reinterpret_cast<uint4*>(&g_feats_h[((size_t)i * B_ + b) * FP_]) = v;
}

// Kernel 2: block = (i-tile of 4, j), 256 threads (8 warps), 4096 blocks.
// Warp w owns 32 b-rows as 2 m16-tiles -> per-thread live regs ~32, cap 40
// (occ 6 blocks = 48 warps/SM = 75%).
// Fragment-packed smem (one LDS.128 per operand class per il):
//   w1p[il][gid][tig] : uint4, q-th u32 = half2(0.5*W1[h=q*8+gid, f=tig*2..+1]), f7->0.5*B1
//   w2p[il][tig]      : uint4, q-th u32 = half2(W2[h=q*8+tig*2], W2[h+1])
__global__ void __launch_bounds__(256, 6) kan_main_kernel(
    const float* __restrict__ W1,   // [I,J,H,7]
    const float* __restrict__ W2,   // [I,J,1,H]
    const float* __restrict__ B1,   // [I,J,H]
    const float* __restrict__ B2,   // [I,J,1]
    float* __restrict__ out)        // [B,J]
{
    __shared__ __align__(16) uint4 w1p[ITILE][8][4];  // [il][gid][tig]
    __shared__ __align__(16) uint4 w2p[ITILE][4];     // [il][tig]
    __shared__ float b2s[ITILE];

    const int j   = blockIdx.y;
    const int i0  = blockIdx.x * ITILE;
    const int tid = threadIdx.x;

    // Stage W1/B1 as packed fragments (ITILE*128 u32 writes)
    {
        unsigned* w1u = reinterpret_cast<unsigned*>(w1p);
        for (int idx = tid; idx < ITILE * 32 * 4; idx += 256) {
            int il = idx >> 7;
            int r  = idx & 127;
            int h  = r >> 2;
            int p  = r & 3;
            size_t ij = (size_t)(i0 + il) * J_ + j;
            const float* w1row = W1 + ij * (H_ * 7) + h * 7;
            float lo = 0.5f * w1row[2 * p];
            float hi = 0.5f * ((p < 3) ? w1row[2 * p + 1] : B1[ij * H_ + h]);
            w1u[il * 128 + (h & 7) * 16 + p * 4 + (h >> 3)] =
                u32h2(__floats2half2_rn(lo, hi));
        }
    }
    // Stage W2 as packed fragments
    {
        unsigned* w2u = reinterpret_cast<unsigned*>(w2p);
        for (int idx = tid; idx < ITILE * 16; idx += 256) {
            int il = idx >> 4;
            int r  = idx & 15;
            int tg = r >> 2;
            int q  = r & 3;
            int h  = q * 8 + tg * 2;
            const float* w2row = W2 + ((size_t)(i0 + il) * J_ + j) * H_;
            w2u[il * 16 + tg * 4 + q] =
                u32h2(__floats2half2_rn(w2row[h], w2row[h + 1]));
        }
    }
    if (tid < ITILE) b2s[tid] = B2[(size_t)(i0 + tid) * J_ + j];
    __syncthreads();

    const int lane = tid & 31, warp = tid >> 5;
    const int gid = lane >> 2;      // fragment row selector
    const int tig = lane & 3;       // fragment col selector
    const int wbase = warp * 32;    // 8 warps x 32 b-rows

    float bsum = 0.0f;
    #pragma unroll
    for (int il = 0; il < ITILE; il++) bsum += b2s[il];

    float acc[2][4] = {};           // [m-tile][k16-MMA D regs]
    const unsigned zero = 0;

    const __half* fbase = g_feats_h + (size_t)i0 * (B_ * FP_)
                        + (wbase + gid) * FP_ + tig * 2;

    #pragma unroll
    for (int il = 0; il < ITILE; il++) {
        // A fragments for both m-tiles (coalesced; L2-hot across j-blocks)
        const __half* fi = fbase + il * (B_ * FP_);
        unsigned A0[2], A1[2];
        #pragma unroll
        for (int mt = 0; mt < 2; mt++) {
            A0[mt] = *reinterpret_cast<const unsigned*>(fi + mt * 16 * FP_);
            A1[mt] = *reinterpret_cast<const unsigned*>(fi + (mt * 16 + 8) * FP_);
        }

        // One LDS.128 each: all W1 fragments (wq) and W2 fragments (bq) for this il
        uint4 wq = w1p[il][gid][tig];   // x,y,z,w = wf for h-groups 0..3
        uint4 bq = w2p[il][tig];        // x,y,z,w = wb for h-groups 0..3

        #pragma unroll
        for (int hgp = 0; hgp < 2; hgp++) {
            unsigned wf0 = hgp ? wq.z : wq.x;
            unsigned wf1 = hgp ? wq.w : wq.y;
            unsigned wb0 = hgp ? bq.z : bq.x;
            unsigned wb1 = hgp ? bq.w : bq.y;

            #pragma unroll
            for (int mt = 0; mt < 2; mt++) {
                // u-MMA, fp16 accumulator: D regs are f16x2
                unsigned u0, u1, u2, u3;
                asm volatile(
                    "mma.sync.aligned.m16n8k8.row.col.f16.f16.f16.f16 "
                    "{%0,%1}, {%2,%3}, {%4}, {%5,%6};"
                    : "=r"(u0), "=r"(u1)
                    : "r"(A0[mt]), "r"(A1[mt]), "r"(wf0), "r"(zero), "r"(zero));
                asm volatile(
                    "mma.sync.aligned.m16n8k8.row.col.f16.f16.f16.f16 "
                    "{%0,%1}, {%2,%3}, {%4}, {%5,%6};"
                    : "=r"(u2), "=r"(u3)
                    : "r"(A0[mt]), "r"(A1[mt]), "r"(wf1), "r"(zero), "r"(zero));

                // silu(t) = u + u*tanh(u), u = t/2 — pure f16x2
                unsigned s0 = hfma2u(u0, tanh2u(u0), u0);
                unsigned s1 = hfma2u(u1, tanh2u(u1), u1);
                unsigned s2 = hfma2u(u2, tanh2u(u2), u2);
                unsigned s3 = hfma2u(u3, tanh2u(u3), u3);

                // h-contraction: m16n8k16, B = W2 replicated over n, fp32 acc
                asm volatile(
                    "mma.sync.aligned.m16n8k16.row.col.f32.f16.f16.f32 "
                    "{%0,%1,%2,%3}, {%4,%5,%6,%7}, {%8,%9}, {%0,%1,%2,%3};"
                    : "+f"(acc[mt][0]), "+f"(acc[mt][1]),
                      "+f"(acc[mt][2]), "+f"(acc[mt][3])
                    : "r"(s0), "r"(s1), "r"(s2), "r"(s3), "r"(wb0), "r"(wb1));
            }
        }
    }

    // Epilogue: tig==0 lanes hold per-b sums. Atomic-accumulate into out[b*J + j].
    if (tig == 0) {
        #pragma unroll
        for (int mt = 0; mt < 2; mt++) {
            int brow = wbase + mt * 16 + gid;
            atomicAdd(&out[(size_t)brow * J_ + j],       acc[mt][0] + bsum);
            atomicAdd(&out[(size_t)(brow + 8) * J_ + j], acc[mt][2] + bsum);
        }
    }
}

extern "C" void kernel_launch(void* const* d_in, const int* in_sizes, int n_in,
                              void* d_out, int out_size) {
    const float* x  = (const float*)d_in[0];
    const float* W1 = (const float*)d_in[1];
    const float* W2 = (const float*)d_in[2];
    const float* B1 = (const float*)d_in[3];
    const float* B2 = (const float*)d_in[4];
    float* out = (float*)d_out;

    feats_kernel<<<(B_ * I_) / 128, 128>>>(x, out);
    kan_main_kernel<<<dim3(IBLKS, J_), 256>>>(W1, W2, B1, B2, out);
}